// round 10
// baseline (speedup 1.0000x reference)
#include <cuda_runtime.h>
#include <cuda_bf16.h>
#include <cstdint>
#include <math.h>

#define K_DIM 128
#define D_DIM 256
#define TILE_M 128
#define NTHREADS 256
#define DC 64
#define SB 144             // smem row stride bytes (72 bf16): conflict-free ldmatrix

// ---- dynamic smem layout (bytes): hi-only tiles ----
#define SMEM_AH    0
#define SMEM_BH    18432
#define SMEM_C2    36864   // 128 f32
#define SMEM_X2    37376   // 128 f32
#define SMEM_BV    37888   // 2*128 f32 (per-half best)   | reused as fallback partials
#define SMEM_BS    38912   // 2*128 f32 (per-half second) | reused as fallback logits
#define SMEM_BI    39936   // 2*128 i32 (per-half idx)
#define SMEM_IDX   40960   // 128 i32
#define SMEM_FCNT  41472   // 1 i32
#define SMEM_FLIST 41476   // 128 i32
#define SMEM_TOTAL 42112

__device__ float g_c2[K_DIM];

// ---------------- PTX helpers ----------------
__device__ __forceinline__ uint32_t smem_u32(const void* p) {
    uint32_t a;
    asm("{ .reg .u64 t; cvta.to.shared.u64 t, %1; cvt.u32.u64 %0, t; }"
        : "=r"(a) : "l"(p));
    return a;
}
__device__ __forceinline__ void ldsm4(uint32_t* r, uint32_t addr) {
    asm volatile("ldmatrix.sync.aligned.m8n8.x4.shared.b16 {%0,%1,%2,%3}, [%4];"
                 : "=r"(r[0]), "=r"(r[1]), "=r"(r[2]), "=r"(r[3]) : "r"(addr));
}
__device__ __forceinline__ void mma_bf16(float* d, const uint32_t* a, const uint32_t* b) {
    asm volatile("mma.sync.aligned.m16n8k16.row.col.f32.bf16.bf16.f32 "
                 "{%0,%1,%2,%3}, {%4,%5,%6,%7}, {%8,%9}, {%0,%1,%2,%3};"
                 : "+f"(d[0]), "+f"(d[1]), "+f"(d[2]), "+f"(d[3])
                 : "r"(a[0]), "r"(a[1]), "r"(a[2]), "r"(a[3]), "r"(b[0]), "r"(b[1]));
}

__device__ __forceinline__ uint32_t pack_bf2(float a, float b) {
    __nv_bfloat16 ha = __float2bfloat16_rn(a), hb = __float2bfloat16_rn(b);
    uint16_t ra = *reinterpret_cast<uint16_t*>(&ha);
    uint16_t rb = *reinterpret_cast<uint16_t*>(&hb);
    return (uint32_t)ra | ((uint32_t)rb << 16);
}
// hi-only convert + store (no lo split)
__device__ __forceinline__ void cvt_store(char* dst, uint32_t off, float4 v) {
    *reinterpret_cast<uint2*>(dst + off) =
        make_uint2(pack_bf2(v.x, v.y), pack_bf2(v.z, v.w));
}

// ---------------- prep: ||c_k||^2 ----------------
__global__ void prep_kernel(const float* __restrict__ C) {
    int k = threadIdx.x;
    float s = 0.f;
    const float* row = C + (size_t)k * D_DIM;
#pragma unroll 8
    for (int d = 0; d < D_DIM; ++d) s = fmaf(row[d], row[d], s);
    g_c2[k] = s;
}

// ---------------- main ----------------
__global__ __launch_bounds__(NTHREADS, 2)
void assign_kernel(const float* __restrict__ seq, const float* __restrict__ u,
                   const float* __restrict__ C, float* __restrict__ assign,
                   int N) {
    extern __shared__ char smem[];
    const uint32_t sm = smem_u32(smem);
    const int tid = threadIdx.x;
    const int wid = tid >> 5;
    const int lane = tid & 31;
    const int row0 = blockIdx.x * TILE_M;

    float* c2s = (float*)(smem + SMEM_C2);
    float* x2s = (float*)(smem + SMEM_X2);
    float* bvs = (float*)(smem + SMEM_BV);
    float* bss = (float*)(smem + SMEM_BS);
    int*   bis = (int*)(smem + SMEM_BI);
    int*   idxs = (int*)(smem + SMEM_IDX);
    int*   fcnt = (int*)(smem + SMEM_FCNT);
    int*   flist = (int*)(smem + SMEM_FLIST);

    if (tid < K_DIM) c2s[tid] = g_c2[tid];
    if (tid == 0) *fcnt = 0;

    const int wr = wid >> 1;       // 0..3: rows wr*32..+31
    const int wc = wid & 1;        // 0..1: cols wc*64..+63

    float acc[2][8][4];
#pragma unroll
    for (int mi = 0; mi < 2; mi++)
#pragma unroll
        for (int ni = 0; ni < 8; ni++)
#pragma unroll
            for (int j = 0; j < 4; j++) acc[mi][ni][j] = 0.f;

    float x2p[8];                  // deferred x2 partials, one per (row,c4) slot
#pragma unroll
    for (int i = 0; i < 8; i++) x2p[i] = 0.f;

    for (int ch = 0; ch < 4; ++ch) {
        if (ch) __syncthreads();   // prior tiles fully consumed

        // ---- load + convert A tile (hi only); accumulate x2 partials in regs ----
#pragma unroll
        for (int i = 0; i < 8; ++i) {
            int f = tid + NTHREADS * i;     // 0..2047
            int row = f >> 4;
            int c4 = f & 15;
            int grow = row0 + row;
            float4 v = make_float4(0.f, 0.f, 0.f, 0.f);
            if (grow < N)
                v = *reinterpret_cast<const float4*>(seq + (size_t)grow * D_DIM + ch * DC + 4 * c4);
            x2p[i] = fmaf(v.x, v.x, fmaf(v.y, v.y, fmaf(v.z, v.z, fmaf(v.w, v.w, x2p[i]))));
            cvt_store(smem + SMEM_AH, (uint32_t)row * SB + c4 * 8, v);
        }
        // ---- load + convert B tile (hi only) ----
#pragma unroll
        for (int i = 0; i < 8; ++i) {
            int f = tid + NTHREADS * i;
            int row = f >> 4;
            int c4 = f & 15;
            float4 v = *reinterpret_cast<const float4*>(C + (size_t)row * D_DIM + ch * DC + 4 * c4);
            cvt_store(smem + SMEM_BH, (uint32_t)row * SB + c4 * 8, v);
        }
        __syncthreads();

        // ---- HMMA mainloop over 4 k16-steps ----
#pragma unroll
        for (int ks = 0; ks < 4; ++ks) {
            uint32_t ah[2][4];
            const uint32_t a_lane_off =
                (uint32_t)(lane & 15) * SB + (uint32_t)(lane >> 4) * 16 + (uint32_t)ks * 32;
#pragma unroll
            for (int mi = 0; mi < 2; ++mi)
                ldsm4(ah[mi], sm + SMEM_AH + (uint32_t)(wr * 32 + mi * 16) * SB + a_lane_off);
            const uint32_t b_lane_off =
                (uint32_t)((lane & 7) + ((lane >> 4) << 3)) * SB +
                (uint32_t)ks * 32 + (uint32_t)(((lane >> 3) & 1) << 4);
#pragma unroll
            for (int np = 0; np < 4; ++np) {
                uint32_t bh[4];
                ldsm4(bh, sm + SMEM_BH + (uint32_t)(wc * 64 + np * 16) * SB + b_lane_off);
#pragma unroll
                for (int mi = 0; mi < 2; ++mi) {
                    mma_bf16(acc[mi][np * 2 + 0], ah[mi], bh + 0);
                    mma_bf16(acc[mi][np * 2 + 1], ah[mi], bh + 2);
                }
            }
        }
    }

    // ---- deferred x2 reduce: 16 lanes share each row ----
#pragma unroll
    for (int i = 0; i < 8; ++i) {
        int f = tid + NTHREADS * i;
        int row = f >> 4;
        float part = x2p[i];
#pragma unroll
        for (int o = 8; o >= 1; o >>= 1)
            part += __shfl_xor_sync(0xffffffffu, part, o);
        if ((lane & 15) == 0) x2s[row] = part;
    }
    __syncthreads();

    // ---- epilogue: logits (fast log), per-row top-2, argmax ----
    const int g = lane >> 2;
    const int tig = lane & 3;
#pragma unroll
    for (int mi = 0; mi < 2; ++mi) {
#pragma unroll
        for (int half = 0; half < 2; ++half) {
            int row = wr * 32 + mi * 16 + g + 8 * half;
            int grow = row0 + row;
            float x2r = x2s[row];
            const float* urow = u + (size_t)(grow < N ? grow : 0) * K_DIM + wc * 64;
            float best = -INFINITY, second = -INFINITY;
            int bidx = 0;
#pragma unroll
            for (int ni = 0; ni < 8; ++ni) {
                int col = ni * 8 + tig * 2;
                float2 uu = *reinterpret_cast<const float2*>(urow + col);
#pragma unroll
                for (int j = 0; j < 2; ++j) {
                    int k = wc * 64 + col + j;
                    float dot = acc[mi][ni][2 * half + j];
                    float sq = fmaxf(x2r - 2.f * dot + c2s[k], 0.f);
                    float uv = j ? uu.y : uu.x;
                    float gb = -__logf(-__logf(uv + 1e-10f) + 1e-10f);
                    float lg = sqrtf(sq) + gb;
                    if (lg > best) { second = best; best = lg; bidx = k; }
                    else if (lg > second) { second = lg; }
                }
            }
#pragma unroll
            for (int o = 1; o <= 2; o <<= 1) {
                float b2 = __shfl_xor_sync(0xffffffffu, best, o);
                float s2 = __shfl_xor_sync(0xffffffffu, second, o);
                int i2 = __shfl_xor_sync(0xffffffffu, bidx, o);
                float lo = fminf(best, b2);
                if (b2 > best || (b2 == best && i2 < bidx)) {
                    second = fmaxf(lo, s2); best = b2; bidx = i2;
                } else {
                    second = fmaxf(lo, second);
                }
            }
            if (tig == 0) {
                bvs[wc * 128 + row] = best;
                bss[wc * 128 + row] = second;
                bis[wc * 128 + row] = bidx;
            }
        }
    }
    __syncthreads();

    // combine halves; flag near-ties for exact fp32 recompute
    if (tid < 128) {
        float v0 = bvs[tid], v1 = bvs[128 + tid];
        float s0 = bss[tid], s1 = bss[128 + tid];
        bool h1 = (v1 > v0);
        float ball = h1 ? v1 : v0;
        float sall = fmaxf(fminf(v0, v1), h1 ? s1 : s0);
        idxs[tid] = h1 ? bis[128 + tid] : bis[tid];
        if (row0 + tid < N && ball - sall < 4e-3f) {
            int p = atomicAdd(fcnt, 1);
            flist[p] = tid;
        }
    }
    __syncthreads();

    // ---- exact fp32 fallback for flagged rows (~0.5/CTA) ----
    int nf = *fcnt;
    for (int f = 0; f < nf; ++f) {
        int row = flist[f];
        int grow = row0 + row;
        {
            int k = tid & 127, h = tid >> 7;
            const float* xr = seq + (size_t)grow * D_DIM + h * 128;
            const float* cr = C + (size_t)k * D_DIM + h * 128;
            float p = 0.f;
#pragma unroll 8
            for (int d = 0; d < 128; ++d) p = fmaf(xr[d], cr[d], p);
            bvs[tid] = p;   // scratch
        }
        __syncthreads();
        if (tid < 128) {
            float dot = bvs[tid] + bvs[tid + 128];
            float sq = fmaxf(x2s[row] - 2.f * dot + c2s[tid], 0.f);
            float uv = u[(size_t)grow * K_DIM + tid];
            bss[tid] = sqrtf(sq) - logf(-logf(uv + 1e-10f) + 1e-10f);
        }
        __syncthreads();
        if (tid == 0) {
            float bv = -INFINITY; int bi = 0;
            for (int k = 0; k < K_DIM; ++k)
                if (bss[k] > bv) { bv = bss[k]; bi = k; }
            idxs[row] = bi;
        }
        __syncthreads();
    }

    // ---- coalesced one-hot store ----
#pragma unroll
    for (int it = 0; it < 16; ++it) {
        int item = tid + NTHREADS * it;   // 0..4095
        int row = item >> 5;
        int c4 = item & 31;
        int grow = row0 + row;
        if (grow < N) {
            int hot = idxs[row];
            float4 o = make_float4(0.f, 0.f, 0.f, 0.f);
            if ((hot >> 2) == c4) reinterpret_cast<float*>(&o)[hot & 3] = 1.0f;
            *reinterpret_cast<float4*>(assign + (size_t)grow * K_DIM + 4 * c4) = o;
        }
    }
}

extern "C" void kernel_launch(void* const* d_in, const int* in_sizes, int n_in,
                              void* d_out, int out_size) {
    const float* seq = (const float*)d_in[0];  // [N,256]
    const float* u   = (const float*)d_in[1];  // [N,128]
    const float* C   = (const float*)d_in[2];  // [128,256]

    const int N = in_sizes[1] / K_DIM;
    float* out = (float*)d_out;
    float* assign = out;

    long long need_both = (long long)N * K_DIM + (long long)K_DIM * D_DIM;
    if ((long long)out_size >= need_both) {
        cudaMemcpyAsync(out, C, (size_t)K_DIM * D_DIM * sizeof(float),
                        cudaMemcpyDeviceToDevice);
        assign = out + K_DIM * D_DIM;
    }

    prep_kernel<<<1, K_DIM>>>(C);

    cudaFuncSetAttribute(assign_kernel,
                         cudaFuncAttributeMaxDynamicSharedMemorySize, SMEM_TOTAL);
    int grid = (N + TILE_M - 1) / TILE_M;
    assign_kernel<<<grid, NTHREADS, SMEM_TOTAL>>>(seq, u, C, assign, N);
}

// round 11
// speedup vs baseline: 1.2663x; 1.2663x over previous
#include <cuda_runtime.h>
#include <cuda_bf16.h>
#include <cstdint>
#include <math.h>

#define K_DIM 128
#define D_DIM 256
#define TILE_M 128
#define NTHREADS 256
#define SBB 528            // B smem row stride bytes (256 bf16 + 16B pad): conflict-free ldsm
#define BIMG (128 * SBB)   // 67584 B

// ---- dynamic smem layout (bytes) ----
#define SMEM_B     0
#define SMEM_MISC  67584
#define SMEM_C2    (SMEM_MISC + 0)      // 128 f32
#define SMEM_X2    (SMEM_MISC + 512)    // 128 f32
#define SMEM_BV    (SMEM_MISC + 1024)   // 2*128 f32 | fallback partials
#define SMEM_BS    (SMEM_MISC + 2048)   // 2*128 f32 | fallback logits
#define SMEM_BI    (SMEM_MISC + 3072)   // 2*128 i32
#define SMEM_IDX   (SMEM_MISC + 4096)   // 128 i32
#define SMEM_FCNT  (SMEM_MISC + 4608)
#define SMEM_FLIST (SMEM_MISC + 4612)   // 128 i32
#define SMEM_TOTAL (SMEM_MISC + 5200)   // 72784 B -> 2 CTAs/SM (regs bind at 2)

__device__ float g_c2[K_DIM];
// Pre-converted B (bf16), full K, padded layout == smem image
__device__ __align__(16) unsigned char g_B[BIMG];

// ---------------- PTX helpers ----------------
__device__ __forceinline__ uint32_t smem_u32(const void* p) {
    uint32_t a;
    asm("{ .reg .u64 t; cvta.to.shared.u64 t, %1; cvt.u32.u64 %0, t; }"
        : "=r"(a) : "l"(p));
    return a;
}
__device__ __forceinline__ void ldsm4(uint32_t* r, uint32_t addr) {
    asm volatile("ldmatrix.sync.aligned.m8n8.x4.shared.b16 {%0,%1,%2,%3}, [%4];"
                 : "=r"(r[0]), "=r"(r[1]), "=r"(r[2]), "=r"(r[3]) : "r"(addr));
}
__device__ __forceinline__ void mma_bf16(float* d, const uint32_t* a, const uint32_t* b) {
    asm volatile("mma.sync.aligned.m16n8k16.row.col.f32.bf16.bf16.f32 "
                 "{%0,%1,%2,%3}, {%4,%5,%6,%7}, {%8,%9}, {%0,%1,%2,%3};"
                 : "+f"(d[0]), "+f"(d[1]), "+f"(d[2]), "+f"(d[3])
                 : "r"(a[0]), "r"(a[1]), "r"(a[2]), "r"(a[3]), "r"(b[0]), "r"(b[1]));
}
__device__ __forceinline__ void cp16(uint32_t smaddr, const void* gaddr) {
    asm volatile("cp.async.ca.shared.global [%0], [%1], 16;"
                 :: "r"(smaddr), "l"(gaddr) : "memory");
}
#define CP_COMMIT() asm volatile("cp.async.commit_group;" ::: "memory")
#define CP_WAIT0()  asm volatile("cp.async.wait_group 0;" ::: "memory")

__device__ __forceinline__ uint32_t pack_bf2(float a, float b) {
    __nv_bfloat16 ha = __float2bfloat16_rn(a), hb = __float2bfloat16_rn(b);
    uint16_t ra = *reinterpret_cast<uint16_t*>(&ha);
    uint16_t rb = *reinterpret_cast<uint16_t*>(&hb);
    return (uint32_t)ra | ((uint32_t)rb << 16);
}

// ---------------- prep (parallel): block b -> c2[b] + B row b bf16 ----------------
__global__ void prep_kernel(const float* __restrict__ C) {
    __shared__ float red[8];
    const int tid = threadIdx.x;     // 0..255 = k
    const int b = blockIdx.x;        // 0..127 = community row

    float v = C[(size_t)b * D_DIM + tid];
    __nv_bfloat16 h = __float2bfloat16_rn(v);
    *reinterpret_cast<uint16_t*>(&g_B[b * SBB + tid * 2]) =
        *reinterpret_cast<uint16_t*>(&h);

    float s = v * v;
#pragma unroll
    for (int o = 16; o >= 1; o >>= 1) s += __shfl_xor_sync(0xffffffffu, s, o);
    if ((tid & 31) == 0) red[tid >> 5] = s;
    __syncthreads();
    if (tid == 0) {
        float t = 0.f;
#pragma unroll
        for (int w = 0; w < 8; ++w) t += red[w];
        g_c2[b] = t;
    }
}

// ---------------- main ----------------
__global__ __launch_bounds__(NTHREADS, 2)
void assign_kernel(const float* __restrict__ seq, const float* __restrict__ u,
                   const float* __restrict__ C, float* __restrict__ assign,
                   int N) {
    extern __shared__ char smem[];
    const uint32_t sm = smem_u32(smem);
    const int tid = threadIdx.x;
    const int wid = tid >> 5;
    const int lane = tid & 31;
    const int row0 = blockIdx.x * TILE_M;

    float* c2s = (float*)(smem + SMEM_C2);
    float* x2s = (float*)(smem + SMEM_X2);
    float* bvs = (float*)(smem + SMEM_BV);
    float* bss = (float*)(smem + SMEM_BS);
    int*   bis = (int*)(smem + SMEM_BI);
    int*   idxs = (int*)(smem + SMEM_IDX);
    int*   fcnt = (int*)(smem + SMEM_FCNT);
    int*   flist = (int*)(smem + SMEM_FLIST);

    // ---- one-time B blit into smem + misc init ----
#pragma unroll
    for (int j = 0; j < 17; ++j) {
        int off = (tid + NTHREADS * j) * 16;
        if (off < BIMG) cp16(sm + SMEM_B + off, g_B + off);
    }
    CP_COMMIT();
    if (tid < K_DIM) c2s[tid] = g_c2[tid];
    if (tid == 0) *fcnt = 0;
    CP_WAIT0();
    __syncthreads();

    const int wr = wid >> 1;       // 0..3: rows wr*32..+31
    const int wc = wid & 1;        // 0..1: cols wc*64..+63

    const int rg = lane >> 2;      // 0..7 row-in-group
    const int tg = lane & 3;       // 0..3 col-pair group

    float acc[2][8][4];
#pragma unroll
    for (int mi = 0; mi < 2; mi++)
#pragma unroll
        for (int ni = 0; ni < 8; ni++)
#pragma unroll
            for (int j = 0; j < 4; j++) acc[mi][ni][j] = 0.f;

    float x2p[4];                  // rows: mi*16 + {rg, rg+8}
#pragma unroll
    for (int i = 0; i < 4; i++) x2p[i] = 0.f;

    // per-thread A row pointers (4 rows), guarded
    const int r0a = wr * 32 + rg;
    bool ok[4];
    const float* ap[4];
#pragma unroll
    for (int mi = 0; mi < 2; ++mi) {
#pragma unroll
        for (int h = 0; h < 2; ++h) {
            int row = r0a + mi * 16 + h * 8;
            int grow = row0 + row;
            ok[mi * 2 + h] = (grow < N);
            ap[mi * 2 + h] = seq + (size_t)(grow < N ? grow : 0) * D_DIM;
        }
    }
    const uint32_t bBase = sm + SMEM_B +
        (uint32_t)(wc * 64 + (lane & 7) + ((lane >> 4) << 3)) * SBB +
        (uint32_t)(((lane >> 3) & 1) << 4);

    // ---- barrier-free mainloop ----
#pragma unroll
    for (int ch = 0; ch < 4; ++ch) {
#pragma unroll
        for (int ks = 0; ks < 4; ++ks) {
            const int c = ch * 64 + ks * 16 + 2 * tg;
            uint32_t ah[2][4];
#pragma unroll
            for (int mi = 0; mi < 2; ++mi) {
                float2 v00 = ok[mi*2+0] ? *reinterpret_cast<const float2*>(ap[mi*2+0] + c)     : make_float2(0.f,0.f);
                float2 v10 = ok[mi*2+1] ? *reinterpret_cast<const float2*>(ap[mi*2+1] + c)     : make_float2(0.f,0.f);
                float2 v01 = ok[mi*2+0] ? *reinterpret_cast<const float2*>(ap[mi*2+0] + c + 8) : make_float2(0.f,0.f);
                float2 v11 = ok[mi*2+1] ? *reinterpret_cast<const float2*>(ap[mi*2+1] + c + 8) : make_float2(0.f,0.f);
                x2p[mi*2+0] = fmaf(v00.x, v00.x, fmaf(v00.y, v00.y,
                              fmaf(v01.x, v01.x, fmaf(v01.y, v01.y, x2p[mi*2+0]))));
                x2p[mi*2+1] = fmaf(v10.x, v10.x, fmaf(v10.y, v10.y,
                              fmaf(v11.x, v11.x, fmaf(v11.y, v11.y, x2p[mi*2+1]))));
                ah[mi][0] = pack_bf2(v00.x, v00.y);
                ah[mi][1] = pack_bf2(v10.x, v10.y);
                ah[mi][2] = pack_bf2(v01.x, v01.y);
                ah[mi][3] = pack_bf2(v11.x, v11.y);
            }
            const uint32_t bk = bBase + (uint32_t)(ch * 128 + ks * 32);
#pragma unroll
            for (int np = 0; np < 4; ++np) {
                uint32_t bh[4];
                ldsm4(bh, bk + (uint32_t)(np * 16) * SBB);
#pragma unroll
                for (int mi = 0; mi < 2; ++mi) {
                    mma_bf16(acc[mi][np * 2 + 0], ah[mi], bh + 0);
                    mma_bf16(acc[mi][np * 2 + 1], ah[mi], bh + 2);
                }
            }
        }
    }

    // ---- x2 reduce over tg lanes (xor 1,2); wc==0 warps write ----
#pragma unroll
    for (int i = 0; i < 4; ++i) {
        float p = x2p[i];
        p += __shfl_xor_sync(0xffffffffu, p, 1);
        p += __shfl_xor_sync(0xffffffffu, p, 2);
        if (wc == 0 && tg == 0) {
            int mi = i >> 1, h = i & 1;
            x2s[wr * 32 + mi * 16 + h * 8 + rg] = p;
        }
    }
    __syncthreads();

    // ---- epilogue: logits (fast log), per-row top-2, argmax ----
#pragma unroll
    for (int mi = 0; mi < 2; ++mi) {
#pragma unroll
        for (int half = 0; half < 2; ++half) {
            int row = wr * 32 + mi * 16 + rg + 8 * half;
            int grow = row0 + row;
            float x2r = x2s[row];
            const float* urow = u + (size_t)(grow < N ? grow : 0) * K_DIM + wc * 64;
            float best = -INFINITY, second = -INFINITY;
            int bidx = 0;
#pragma unroll
            for (int ni = 0; ni < 8; ++ni) {
                int col = ni * 8 + tg * 2;
                float2 uu = *reinterpret_cast<const float2*>(urow + col);
#pragma unroll
                for (int j = 0; j < 2; ++j) {
                    int k = wc * 64 + col + j;
                    float dot = acc[mi][ni][2 * half + j];
                    float sq = fmaxf(x2r - 2.f * dot + c2s[k], 0.f);
                    float uv = j ? uu.y : uu.x;
                    float gb = -__logf(-__logf(uv + 1e-10f) + 1e-10f);
                    float lg = sqrtf(sq) + gb;
                    if (lg > best) { second = best; best = lg; bidx = k; }
                    else if (lg > second) { second = lg; }
                }
            }
#pragma unroll
            for (int o = 1; o <= 2; o <<= 1) {
                float b2 = __shfl_xor_sync(0xffffffffu, best, o);
                float s2 = __shfl_xor_sync(0xffffffffu, second, o);
                int i2 = __shfl_xor_sync(0xffffffffu, bidx, o);
                float lo = fminf(best, b2);
                if (b2 > best || (b2 == best && i2 < bidx)) {
                    second = fmaxf(lo, s2); best = b2; bidx = i2;
                } else {
                    second = fmaxf(lo, second);
                }
            }
            if (tg == 0) {
                bvs[wc * 128 + row] = best;
                bss[wc * 128 + row] = second;
                bis[wc * 128 + row] = bidx;
            }
        }
    }
    __syncthreads();

    // combine halves; flag near-ties for exact fp32 recompute
    if (tid < 128) {
        float v0 = bvs[tid], v1 = bvs[128 + tid];
        float s0 = bss[tid], s1 = bss[128 + tid];
        bool h1 = (v1 > v0);
        float ball = h1 ? v1 : v0;
        float sall = fmaxf(fminf(v0, v1), h1 ? s1 : s0);
        idxs[tid] = h1 ? bis[128 + tid] : bis[tid];
        if (row0 + tid < N && ball - sall < 4e-3f) {
            int p = atomicAdd(fcnt, 1);
            flist[p] = tid;
        }
    }
    __syncthreads();

    // ---- exact fp32 fallback for flagged rows (~0.5/CTA) ----
    int nf = *fcnt;
    for (int f = 0; f < nf; ++f) {
        int row = flist[f];
        int grow = row0 + row;
        {
            int k = tid & 127, h = tid >> 7;
            const float* xr = seq + (size_t)grow * D_DIM + h * 128;
            const float* cr = C + (size_t)k * D_DIM + h * 128;
            float p = 0.f;
#pragma unroll 8
            for (int d = 0; d < 128; ++d) p = fmaf(xr[d], cr[d], p);
            bvs[tid] = p;   // scratch
        }
        __syncthreads();
        if (tid < 128) {
            float dot = bvs[tid] + bvs[tid + 128];
            float sq = fmaxf(x2s[row] - 2.f * dot + c2s[tid], 0.f);
            float uv = u[(size_t)grow * K_DIM + tid];
            bss[tid] = sqrtf(sq) - logf(-logf(uv + 1e-10f) + 1e-10f);
        }
        __syncthreads();
        if (tid == 0) {
            float bv = -INFINITY; int bi = 0;
            for (int k = 0; k < K_DIM; ++k)
                if (bss[k] > bv) { bv = bss[k]; bi = k; }
            idxs[row] = bi;
        }
        __syncthreads();
    }

    // ---- coalesced one-hot store ----
#pragma unroll
    for (int it = 0; it < 16; ++it) {
        int item = tid + NTHREADS * it;   // 0..4095
        int row = item >> 5;
        int c4 = item & 31;
        int grow = row0 + row;
        if (grow < N) {
            int hot = idxs[row];
            float4 o = make_float4(0.f, 0.f, 0.f, 0.f);
            if ((hot >> 2) == c4) reinterpret_cast<float*>(&o)[hot & 3] = 1.0f;
            *reinterpret_cast<float4*>(assign + (size_t)grow * K_DIM + 4 * c4) = o;
        }
    }
}

extern "C" void kernel_launch(void* const* d_in, const int* in_sizes, int n_in,
                              void* d_out, int out_size) {
    const float* seq = (const float*)d_in[0];  // [N,256]
    const float* u   = (const float*)d_in[1];  // [N,128]
    const float* C   = (const float*)d_in[2];  // [128,256]

    const int N = in_sizes[1] / K_DIM;
    float* out = (float*)d_out;
    float* assign = out;

    long long need_both = (long long)N * K_DIM + (long long)K_DIM * D_DIM;
    if ((long long)out_size >= need_both) {
        cudaMemcpyAsync(out, C, (size_t)K_DIM * D_DIM * sizeof(float),
                        cudaMemcpyDeviceToDevice);
        assign = out + K_DIM * D_DIM;
    }

    prep_kernel<<<128, 256>>>(C);

    cudaFuncSetAttribute(assign_kernel,
                         cudaFuncAttributeMaxDynamicSharedMemorySize, SMEM_TOTAL);
    int grid = (N + TILE_M - 1) / TILE_M;
    assign_kernel<<<grid, NTHREADS, SMEM_TOTAL>>>(seq, u, C, assign, N);
}